// round 15
// baseline (speedup 1.0000x reference)
#include <cuda_runtime.h>
#include <utility>
#include <cstdint>

// ---------------------------------------------------------------------------
// Problem constants (fixed: LS=[0,1,2], OFF=[0,1,4], 11 paths, MUL=32, dim=9)
// ---------------------------------------------------------------------------
#define BASE_DIM 9
#define MUL 32
#define NPATHS 11
#define MAX_NODES 10000
#define ROW (MUL * BASE_DIM) /* 288 */
#define ROWB (ROW * 4)       /* 1152 bytes */

struct BEntry { int i, j, k, p; };
struct BTable { BEntry e[96]; int n; };

constexpr BTable build_table() {
    constexpr int ls[3]  = {0, 1, 2};
    constexpr int off[3] = {0, 1, 4};
    constexpr int paths[NPATHS][3] = {
        {0,0,0},{1,1,0},{2,2,0},
        {0,1,1},{1,0,1},{1,2,1},{2,1,1},
        {0,2,2},{1,1,2},{2,0,2},{2,2,2}};
    BTable t{};
    t.n = 0;
    for (int p = 0; p < NPATHS; ++p) {
        const int la = ls[paths[p][0]], lb = ls[paths[p][1]], lc = ls[paths[p][2]];
        for (int m1 = -la; m1 <= la; ++m1)
        for (int m2 = -lb; m2 <= lb; ++m2)
        for (int m3 = -lc; m3 <= lc; ++m3) {
            const int a = m1 < 0 ? -m1 : m1;
            const int b = m2 < 0 ? -m2 : m2;
            const int c = m3 < 0 ? -m3 : m3;
            const int d = a > b ? a - b : b - a;
            if (c != a + b && c != d) continue;
            const int negs = (m1 < 0) + (m2 < 0) + (m3 < 0);
            if (negs & 1) continue;
            t.e[t.n].i = off[paths[p][0]] + la + m1;
            t.e[t.n].j = off[paths[p][1]] + lb + m2;
            t.e[t.n].k = off[paths[p][2]] + lc + m3;
            t.e[t.n].p = p;
            ++t.n;
        }
    }
    return t;
}

constexpr BTable TAB = build_table();
constexpr int NS = TAB.n;
static_assert(NS == 83, "expected 83 structural nonzeros");

struct PStarts { int v[NPATHS + 1]; };
constexpr PStarts build_pstarts() {
    PStarts r{};
    for (int p = 0; p <= NPATHS; ++p) {
        int c = 0;
        for (int s = 0; s < NS; ++s) if (TAB.e[s].p < p) ++c;
        r.v[p] = c;
    }
    return r;
}
constexpr PStarts PSTART = build_pstarts();

constexpr int PATH_K_BASE[NPATHS] = {0,0,0, 1,1,1,1, 4,4,4,4};
constexpr int PATH_K_CNT [NPATHS] = {1,1,1, 3,3,3,3, 5,5,5,5};

__constant__ BTable c_TAB = TAB;
// packed (v, v) f32x2 pairs of the 83 lane-invariant w3j entry values
__constant__ unsigned long long c_VAL2[96];

// ---------------------------------------------------------------------------
// Device scratch
// ---------------------------------------------------------------------------
__device__ __align__(16) float g_scatter[(size_t)MAX_NODES * ROW]; // 11.52 MB
__device__ unsigned long long g_cval2[96];

// ---------------------------------------------------------------------------
// f32x2 packed helpers (sm_100+)
// ---------------------------------------------------------------------------
__device__ __forceinline__ unsigned long long pk2(float lo, float hi) {
    unsigned long long r;
    asm("mov.b64 %0, {%1, %2};" : "=l"(r) : "f"(lo), "f"(hi));
    return r;
}
__device__ __forceinline__ void upk2(float& lo, float& hi,
                                     unsigned long long v) {
    asm("mov.b64 {%0, %1}, %2;" : "=f"(lo), "=f"(hi) : "l"(v));
}
__device__ __forceinline__ unsigned long long mul2(unsigned long long a,
                                                   unsigned long long b) {
    unsigned long long r;
    asm("mul.rn.f32x2 %0, %1, %2;" : "=l"(r) : "l"(a), "l"(b));
    return r;
}
__device__ __forceinline__ unsigned long long fma2(unsigned long long a,
                                                   unsigned long long b,
                                                   unsigned long long c) {
    unsigned long long r;
    asm("fma.rn.f32x2 %0, %1, %2, %3;" : "=l"(r) : "l"(a), "l"(b), "l"(c));
    return r;
}

// ---------------------------------------------------------------------------
// K1: scatter-add x2 rows into node rows via 128-bit vector reductions.
//     Block 0 (threads 0..95) also extracts the 83 w3j entry values (packed).
// ---------------------------------------------------------------------------
__global__ void scatter_kernel(const float* __restrict__ x2,
                               const int* __restrict__ idxs, int E,
                               const float* __restrict__ w3j) {
    if (blockIdx.x == 0 && threadIdx.x < 96) {
        const int s = threadIdx.x;
        float v = 0.f;
        if (s < NS) {
            const BEntry en = c_TAB.e[s];
            v = w3j[en.p * 729 + en.i * 81 + en.j * 9 + en.k];
        }
        const unsigned long long ub = (unsigned long long)__float_as_uint(v);
        g_cval2[s] = (ub << 32) | ub;
    }
    const int t = blockIdx.x * blockDim.x + threadIdx.x;
    const int total = E * (ROW / 4);
    if (t >= total) return;
    const int e = t / (ROW / 4);
    const int c = t - e * (ROW / 4);
    const int node = idxs[e];
    const float4 v = reinterpret_cast<const float4*>(x2)[t];
    float* dst = g_scatter + (size_t)node * ROW + c * 4;
    asm volatile(
        "red.relaxed.gpu.global.add.v4.f32 [%0], {%1, %2, %3, %4};"
        :: "l"(__cvta_generic_to_global(dst)),
           "f"(v.x), "f"(v.y), "f"(v.z), "f"(v.w)
        : "memory");
}

// ---------------------------------------------------------------------------
// Packed contraction codegen: each u64 holds (edge0, edge1) lanes of f32x2
// ---------------------------------------------------------------------------
template <int P, int S, int SEND>
__device__ __forceinline__ void path_entries2(unsigned long long* pacc,
                                              const unsigned long long* a,
                                              const unsigned long long* b) {
    if constexpr (S < SEND) {
        constexpr int i = TAB.e[S].i;
        constexpr int j = TAB.e[S].j;
        constexpr int kk = TAB.e[S].k - PATH_K_BASE[P];
        pacc[kk] = fma2(mul2(a[i], b[j]), c_VAL2[S], pacc[kk]);
        path_entries2<P, S + 1, SEND>(pacc, a, b);
    }
}

template <int P>
__device__ __forceinline__ void do_path2(unsigned long long* acc,
                                         const unsigned long long* a,
                                         const unsigned long long* b,
                                         const float* __restrict__ wsm,
                                         int lane) {
    constexpr int kc = PATH_K_CNT[P];
    unsigned long long pacc[5] = {0ULL, 0ULL, 0ULL, 0ULL, 0ULL};
    path_entries2<P, PSTART.v[P], PSTART.v[P + 1]>(pacc, a, b);
    const float w = wsm[P * 32 + lane];
    const unsigned long long w2 = pk2(w, w);
#pragma unroll
    for (int kk = 0; kk < kc; ++kk)
        acc[kk] = fma2(w2, pacc[kk], acc[kk]);
}

// ---------------------------------------------------------------------------
// TMA 1D bulk helpers
// ---------------------------------------------------------------------------
__device__ __forceinline__ uint32_t s2u(const void* p) {
    return (uint32_t)__cvta_generic_to_shared(p);
}
__device__ __forceinline__ void bulk_ld(uint32_t dst_smem, const void* src,
                                        uint32_t bytes, uint32_t mbar) {
    asm volatile(
        "cp.async.bulk.shared::cta.global.mbarrier::complete_tx::bytes "
        "[%0], [%1], %2, [%3];"
        :: "r"(dst_smem), "l"(src), "r"(bytes), "r"(mbar) : "memory");
}
__device__ __forceinline__ void bulk_st(void* dst, uint32_t src_smem,
                                        uint32_t bytes) {
    asm volatile(
        "cp.async.bulk.global.shared::cta.bulk_group [%0], [%1], %2;"
        :: "l"(dst), "r"(src_smem), "r"(bytes) : "memory");
}
__device__ __forceinline__ void mbar_init(uint32_t mbar, uint32_t cnt) {
    asm volatile("mbarrier.init.shared::cta.b64 [%0], %1;"
                 :: "r"(mbar), "r"(cnt) : "memory");
}
__device__ __forceinline__ void mbar_expect_tx(uint32_t mbar, uint32_t bytes) {
    asm volatile("mbarrier.arrive.expect_tx.shared::cta.b64 _, [%0], %1;"
                 :: "r"(mbar), "r"(bytes) : "memory");
}
__device__ __forceinline__ void mbar_wait(uint32_t mbar, uint32_t phase) {
    uint32_t done;
    do {
        asm volatile(
            "{\n\t.reg .pred p;\n\t"
            "mbarrier.try_wait.parity.acquire.cta.shared::cta.b64 p, [%1], %2, 0x989680;\n\t"
            "selp.b32 %0, 1, 0, p;\n\t}"
            : "=r"(done) : "r"(mbar), "r"(phase) : "memory");
    } while (!done);
}

// ---------------------------------------------------------------------------
// K2: packed per-edge-pair contraction, all-TMA, x1/out buffer PING-PONG so
//     the store drain is wait_group 1 (off the critical path).
//     warp = pair of consecutive edges, lane = u. 6 warps/block, static smem.
// ---------------------------------------------------------------------------
#define CWARPS 6

struct __align__(16) WarpBuf {
    float x1b[2][2 * ROW]; // ping-pong: TMA dst for x1 pair AND store source
    float bb[2 * ROW];     // gathered node rows (TMA destination)
};

__global__ __launch_bounds__(CWARPS * 32, 5)
void compute_kernel(const float* __restrict__ x1, const int* __restrict__ idxs,
                    const float* __restrict__ weights, float* __restrict__ out,
                    int nPairs, int totalWarps) {
    __shared__ WarpBuf wb[CWARPS];
    __shared__ __align__(8) unsigned long long mbars[CWARPS];
    __shared__ float wsm[NPATHS * 32]; // [p][u]

    const int lane = threadIdx.x & 31;
    const int wip  = threadIdx.x >> 5;
    const int gw   = blockIdx.x * CWARPS + wip;

    float* bb  = wb[wip].bb;
    const uint32_t bs = s2u(bb);
    const uint32_t mb = s2u(&mbars[wip]);
    const uint32_t x1s[2] = { s2u(wb[wip].x1b[0]), s2u(wb[wip].x1b[1]) };

    for (int t = threadIdx.x; t < NPATHS * 32; t += CWARPS * 32) {
        const int p = t >> 5;
        const int u = t & 31;
        wsm[t] = weights[u * NPATHS + p];
    }
    if (lane == 0) mbar_init(mb, 1);
    __syncthreads();

    uint32_t phase = 0;
    int sel = 0;

    for (int pe = gw; pe < nPairs; pe += totalWarps) {
        const int e0 = 2 * pe;
        __syncwarp(); // all lanes done with bb / previous buffers

        // 1) issue input loads. x1 goes into buffer `sel`; the store that read
        //    this buffer was committed two iterations ago -> wait_group 1
        //    (allow the most recent store to remain in flight) is enough.
        if (lane == 0) {
            asm volatile("cp.async.bulk.wait_group 1;" ::: "memory");
            const int2 nn = *reinterpret_cast<const int2*>(idxs + e0);
            mbar_expect_tx(mb, 4 * ROWB);
            bulk_ld(x1s[sel], x1 + (size_t)e0 * ROW, 2 * ROWB, mb);
            bulk_ld(bs, g_scatter + (size_t)nn.x * ROW, ROWB, mb);
            bulk_ld(bs + ROWB, g_scatter + (size_t)nn.y * ROW, ROWB, mb);
        }
        mbar_wait(mb, phase);
        phase ^= 1;

        float* x1b = wb[wip].x1b[sel];

        // 2) pack (edge0, edge1) lane-private values into f32x2 registers
        unsigned long long a[9], b[9];
#pragma unroll
        for (int i = 0; i < 9; ++i)
            a[i] = pk2(x1b[lane * 9 + i], x1b[ROW + lane * 9 + i]);
#pragma unroll
        for (int j = 0; j < 9; ++j)
            b[j] = pk2(bb[lane * 9 + j], bb[ROW + lane * 9 + j]);

        // 3) packed contraction; results overwrite the SAME lane-private
        //    regions of x1b[sel] (each lane reads/writes only its own 9+9)
        {
            unsigned long long acc[1] = {0ULL};
            do_path2<0>(acc, a, b, wsm, lane);
            do_path2<1>(acc, a, b, wsm, lane);
            do_path2<2>(acc, a, b, wsm, lane);
            float lo, hi;
            upk2(lo, hi, acc[0]);
            x1b[lane * 9 + 0] = lo;
            x1b[ROW + lane * 9 + 0] = hi;
        }
        {
            unsigned long long acc[3] = {0ULL, 0ULL, 0ULL};
            do_path2<3>(acc, a, b, wsm, lane);
            do_path2<4>(acc, a, b, wsm, lane);
            do_path2<5>(acc, a, b, wsm, lane);
            do_path2<6>(acc, a, b, wsm, lane);
#pragma unroll
            for (int kk = 0; kk < 3; ++kk) {
                float lo, hi;
                upk2(lo, hi, acc[kk]);
                x1b[lane * 9 + 1 + kk] = lo;
                x1b[ROW + lane * 9 + 1 + kk] = hi;
            }
        }
        {
            unsigned long long acc[5] = {0ULL, 0ULL, 0ULL, 0ULL, 0ULL};
            do_path2<7>(acc, a, b, wsm, lane);
            do_path2<8>(acc, a, b, wsm, lane);
            do_path2<9>(acc, a, b, wsm, lane);
            do_path2<10>(acc, a, b, wsm, lane);
#pragma unroll
            for (int kk = 0; kk < 5; ++kk) {
                float lo, hi;
                upk2(lo, hi, acc[kk]);
                x1b[lane * 9 + 4 + kk] = lo;
                x1b[ROW + lane * 9 + 4 + kk] = hi;
            }
        }
        __syncwarp(); // all lanes' result STS visible before the bulk store

        // 4) ship the pair's output from x1b[sel]; flip buffers
        if (lane == 0) {
            asm volatile("fence.proxy.async.shared::cta;" ::: "memory");
            bulk_st(out + (size_t)e0 * ROW, x1s[sel], 2 * ROWB);
            asm volatile("cp.async.bulk.commit_group;" ::: "memory");
        }
        sel ^= 1;
    }
    if (lane == 0)
        asm volatile("cp.async.bulk.wait_group 0;" ::: "memory");
}

// ---------------------------------------------------------------------------
// launch
// ---------------------------------------------------------------------------
extern "C" void kernel_launch(void* const* d_in, const int* in_sizes, int n_in,
                              void* d_out, int out_size) {
    const float* x1   = (const float*)d_in[0];
    const float* x2   = (const float*)d_in[1];
    const int*   idxs = (const int*)d_in[2];

    const float* w3j = nullptr;
    const float* weights = nullptr;
    for (int i = 3; i < n_in; ++i) {
        if (in_sizes[i] == NPATHS * 729) w3j = (const float*)d_in[i];
        else if (in_sizes[i] == MUL * NPATHS) weights = (const float*)d_in[i];
    }

    const int E = in_sizes[0] / ROW;
    float* out = (float*)d_out;

    // driver-optimized zeroing of the scatter buffer (graph memset node)
    void* scatter_dev = nullptr;
    cudaGetSymbolAddress(&scatter_dev, g_scatter);
    cudaMemsetAsync(scatter_dev, 0, (size_t)MAX_NODES * ROW * sizeof(float), 0);

    // scatter + packed w3j extraction fused
    scatter_kernel<<<(E * (ROW / 4) + 255) / 256, 256>>>(x2, idxs, E, w3j);

    void* cval_dev = nullptr;
    cudaGetSymbolAddress(&cval_dev, g_cval2);
    cudaMemcpyToSymbolAsync(c_VAL2, cval_dev, 96 * sizeof(unsigned long long),
                            0, cudaMemcpyDeviceToDevice, 0);

    const int nPairs = E / 2;  // E = 100000 (even)
    const int blocks = 740;    // 148 SMs * 5 blocks of 6 warps
    const int totalWarps = blocks * CWARPS;
    compute_kernel<<<blocks, CWARPS * 32>>>(x1, idxs, weights, out, nPairs,
                                            totalWarps);
}

// round 16
// speedup vs baseline: 1.1014x; 1.1014x over previous
#include <cuda_runtime.h>
#include <utility>
#include <cstdint>

// ---------------------------------------------------------------------------
// Problem constants (fixed: LS=[0,1,2], OFF=[0,1,4], 11 paths, MUL=32, dim=9)
// ---------------------------------------------------------------------------
#define BASE_DIM 9
#define MUL 32
#define NPATHS 11
#define MAX_NODES 10000
#define ROW (MUL * BASE_DIM) /* 288 */
#define ROWB (ROW * 4)       /* 1152 bytes */

struct BEntry { int i, j, k, p; };
struct BTable { BEntry e[96]; int n; };

constexpr BTable build_table() {
    constexpr int ls[3]  = {0, 1, 2};
    constexpr int off[3] = {0, 1, 4};
    constexpr int paths[NPATHS][3] = {
        {0,0,0},{1,1,0},{2,2,0},
        {0,1,1},{1,0,1},{1,2,1},{2,1,1},
        {0,2,2},{1,1,2},{2,0,2},{2,2,2}};
    BTable t{};
    t.n = 0;
    for (int p = 0; p < NPATHS; ++p) {
        const int la = ls[paths[p][0]], lb = ls[paths[p][1]], lc = ls[paths[p][2]];
        for (int m1 = -la; m1 <= la; ++m1)
        for (int m2 = -lb; m2 <= lb; ++m2)
        for (int m3 = -lc; m3 <= lc; ++m3) {
            const int a = m1 < 0 ? -m1 : m1;
            const int b = m2 < 0 ? -m2 : m2;
            const int c = m3 < 0 ? -m3 : m3;
            const int d = a > b ? a - b : b - a;
            if (c != a + b && c != d) continue;
            const int negs = (m1 < 0) + (m2 < 0) + (m3 < 0);
            if (negs & 1) continue;
            t.e[t.n].i = off[paths[p][0]] + la + m1;
            t.e[t.n].j = off[paths[p][1]] + lb + m2;
            t.e[t.n].k = off[paths[p][2]] + lc + m3;
            t.e[t.n].p = p;
            ++t.n;
        }
    }
    return t;
}

constexpr BTable TAB = build_table();
constexpr int NS = TAB.n;
static_assert(NS == 83, "expected 83 structural nonzeros");

struct PStarts { int v[NPATHS + 1]; };
constexpr PStarts build_pstarts() {
    PStarts r{};
    for (int p = 0; p <= NPATHS; ++p) {
        int c = 0;
        for (int s = 0; s < NS; ++s) if (TAB.e[s].p < p) ++c;
        r.v[p] = c;
    }
    return r;
}
constexpr PStarts PSTART = build_pstarts();

constexpr int PATH_K_BASE[NPATHS] = {0,0,0, 1,1,1,1, 4,4,4,4};
constexpr int PATH_K_CNT [NPATHS] = {1,1,1, 3,3,3,3, 5,5,5,5};

__constant__ BTable c_TAB = TAB;
// packed (v, v) f32x2 pairs of the 83 lane-invariant w3j entry values
__constant__ unsigned long long c_VAL2[96];

// ---------------------------------------------------------------------------
// Device scratch
// ---------------------------------------------------------------------------
__device__ __align__(16) float g_scatter[(size_t)MAX_NODES * ROW]; // 11.52 MB
__device__ unsigned long long g_cval2[96];

// ---------------------------------------------------------------------------
// f32x2 packed helpers (sm_100+)
// ---------------------------------------------------------------------------
__device__ __forceinline__ unsigned long long pk2(float lo, float hi) {
    unsigned long long r;
    asm("mov.b64 %0, {%1, %2};" : "=l"(r) : "f"(lo), "f"(hi));
    return r;
}
__device__ __forceinline__ void upk2(float& lo, float& hi,
                                     unsigned long long v) {
    asm("mov.b64 {%0, %1}, %2;" : "=f"(lo), "=f"(hi) : "l"(v));
}
__device__ __forceinline__ unsigned long long mul2(unsigned long long a,
                                                   unsigned long long b) {
    unsigned long long r;
    asm("mul.rn.f32x2 %0, %1, %2;" : "=l"(r) : "l"(a), "l"(b));
    return r;
}
__device__ __forceinline__ unsigned long long fma2(unsigned long long a,
                                                   unsigned long long b,
                                                   unsigned long long c) {
    unsigned long long r;
    asm("fma.rn.f32x2 %0, %1, %2, %3;" : "=l"(r) : "l"(a), "l"(b), "l"(c));
    return r;
}

// ---------------------------------------------------------------------------
// K1: scatter-add x2 rows into node rows via 128-bit vector reductions.
//     Each thread handles chunks c and c+36 of one edge: 2 back-to-back
//     LDG.128 (MLP=2), one idxs load per 2 chunks, half the threads.
//     Block 0 (threads 0..95) also extracts the 83 w3j entry values (packed).
// ---------------------------------------------------------------------------
#define HALF_CHUNKS 36 /* ROW/4/2 */

__global__ void scatter_kernel(const float* __restrict__ x2,
                               const int* __restrict__ idxs, int E,
                               const float* __restrict__ w3j) {
    if (blockIdx.x == 0 && threadIdx.x < 96) {
        const int s = threadIdx.x;
        float v = 0.f;
        if (s < NS) {
            const BEntry en = c_TAB.e[s];
            v = w3j[en.p * 729 + en.i * 81 + en.j * 9 + en.k];
        }
        const unsigned long long ub = (unsigned long long)__float_as_uint(v);
        g_cval2[s] = (ub << 32) | ub;
    }
    const int t = blockIdx.x * blockDim.x + threadIdx.x;
    const int total = E * HALF_CHUNKS;
    if (t >= total) return;
    const int e = t / HALF_CHUNKS;
    const int c = t - e * HALF_CHUNKS;
    const int node = __ldg(idxs + e);
    // two independent 128-bit loads issued back-to-back
    const float4* src = reinterpret_cast<const float4*>(x2) + (size_t)e * (ROW / 4);
    const float4 v0 = __ldg(src + c);
    const float4 v1 = __ldg(src + c + HALF_CHUNKS);
    float* dst = g_scatter + (size_t)node * ROW + c * 4;
    asm volatile(
        "red.relaxed.gpu.global.add.v4.f32 [%0], {%1, %2, %3, %4};"
        :: "l"(__cvta_generic_to_global(dst)),
           "f"(v0.x), "f"(v0.y), "f"(v0.z), "f"(v0.w)
        : "memory");
    asm volatile(
        "red.relaxed.gpu.global.add.v4.f32 [%0], {%1, %2, %3, %4};"
        :: "l"(__cvta_generic_to_global(dst + HALF_CHUNKS * 4)),
           "f"(v1.x), "f"(v1.y), "f"(v1.z), "f"(v1.w)
        : "memory");
}

// ---------------------------------------------------------------------------
// Packed contraction codegen: each u64 holds (edge0, edge1) lanes of f32x2
// ---------------------------------------------------------------------------
template <int P, int S, int SEND>
__device__ __forceinline__ void path_entries2(unsigned long long* pacc,
                                              const unsigned long long* a,
                                              const unsigned long long* b) {
    if constexpr (S < SEND) {
        constexpr int i = TAB.e[S].i;
        constexpr int j = TAB.e[S].j;
        constexpr int kk = TAB.e[S].k - PATH_K_BASE[P];
        pacc[kk] = fma2(mul2(a[i], b[j]), c_VAL2[S], pacc[kk]);
        path_entries2<P, S + 1, SEND>(pacc, a, b);
    }
}

template <int P>
__device__ __forceinline__ void do_path2(unsigned long long* acc,
                                         const unsigned long long* a,
                                         const unsigned long long* b,
                                         const float* __restrict__ wsm,
                                         int lane) {
    constexpr int kc = PATH_K_CNT[P];
    unsigned long long pacc[5] = {0ULL, 0ULL, 0ULL, 0ULL, 0ULL};
    path_entries2<P, PSTART.v[P], PSTART.v[P + 1]>(pacc, a, b);
    const float w = wsm[P * 32 + lane];
    const unsigned long long w2 = pk2(w, w);
#pragma unroll
    for (int kk = 0; kk < kc; ++kk)
        acc[kk] = fma2(w2, pacc[kk], acc[kk]);
}

// ---------------------------------------------------------------------------
// TMA 1D bulk helpers
// ---------------------------------------------------------------------------
__device__ __forceinline__ uint32_t s2u(const void* p) {
    return (uint32_t)__cvta_generic_to_shared(p);
}
__device__ __forceinline__ void bulk_ld(uint32_t dst_smem, const void* src,
                                        uint32_t bytes, uint32_t mbar) {
    asm volatile(
        "cp.async.bulk.shared::cta.global.mbarrier::complete_tx::bytes "
        "[%0], [%1], %2, [%3];"
        :: "r"(dst_smem), "l"(src), "r"(bytes), "r"(mbar) : "memory");
}
__device__ __forceinline__ void bulk_st(void* dst, uint32_t src_smem,
                                        uint32_t bytes) {
    asm volatile(
        "cp.async.bulk.global.shared::cta.bulk_group [%0], [%1], %2;"
        :: "l"(dst), "r"(src_smem), "r"(bytes) : "memory");
}
__device__ __forceinline__ void mbar_init(uint32_t mbar, uint32_t cnt) {
    asm volatile("mbarrier.init.shared::cta.b64 [%0], %1;"
                 :: "r"(mbar), "r"(cnt) : "memory");
}
__device__ __forceinline__ void mbar_expect_tx(uint32_t mbar, uint32_t bytes) {
    asm volatile("mbarrier.arrive.expect_tx.shared::cta.b64 _, [%0], %1;"
                 :: "r"(mbar), "r"(bytes) : "memory");
}
__device__ __forceinline__ void mbar_wait(uint32_t mbar, uint32_t phase) {
    uint32_t done;
    do {
        asm volatile(
            "{\n\t.reg .pred p;\n\t"
            "mbarrier.try_wait.parity.acquire.cta.shared::cta.b64 p, [%1], %2, 0x989680;\n\t"
            "selp.b32 %0, 1, 0, p;\n\t}"
            : "=r"(done) : "r"(mbar), "r"(phase) : "memory");
    } while (!done);
}

// ---------------------------------------------------------------------------
// K2: packed per-edge-pair contraction, TMA bulk in/out (R12 structure,
//     byte-identical). warp = pair of consecutive edges, lane = u.
//     Out reuses the x1 buffer.
// ---------------------------------------------------------------------------
#define CWARPS 8

struct __align__(16) WarpBuf {
    float x1b[2 * ROW]; // in: x1 pair rows; out: result pair rows
    float bb[2 * ROW];  // gathered node rows for the two edges
};

__global__ __launch_bounds__(CWARPS * 32, 4)
void compute_kernel(const float* __restrict__ x1, const int* __restrict__ idxs,
                    const float* __restrict__ weights, float* __restrict__ out,
                    int nPairs, int totalWarps) {
    __shared__ WarpBuf wb[CWARPS];
    __shared__ __align__(8) unsigned long long mbars[CWARPS];
    __shared__ float wsm[NPATHS * 32]; // [p][u]

    const int lane = threadIdx.x & 31;
    const int wip  = threadIdx.x >> 5;
    const int gw   = blockIdx.x * CWARPS + wip;

    float* x1b = wb[wip].x1b;
    float* bb  = wb[wip].bb;
    const uint32_t x1s = s2u(x1b);
    const uint32_t bs  = s2u(bb);
    const uint32_t mb  = s2u(&mbars[wip]);

    for (int t = threadIdx.x; t < NPATHS * 32; t += CWARPS * 32) {
        const int p = t >> 5;
        const int u = t & 31;
        wsm[t] = weights[u * NPATHS + p];
    }
    if (lane == 0) mbar_init(mb, 1);
    __syncthreads();

    uint32_t phase = 0;

    for (int pe = gw; pe < nPairs; pe += totalWarps) {
        const int e0 = 2 * pe;
        __syncwarp(); // all lanes past previous compute (bb/x1b reads done)
        if (lane == 0) {
            const int2 nn = *reinterpret_cast<const int2*>(idxs + e0);
            // previous bulk store reads x1b; must drain before TMA reload
            asm volatile("cp.async.bulk.wait_group 0;" ::: "memory");
            mbar_expect_tx(mb, 4 * ROWB);
            bulk_ld(x1s, x1 + (size_t)e0 * ROW, 2 * ROWB, mb);
            bulk_ld(bs, g_scatter + (size_t)nn.x * ROW, ROWB, mb);
            bulk_ld(bs + ROWB, g_scatter + (size_t)nn.y * ROW, ROWB, mb);
        }
        mbar_wait(mb, phase);
        phase ^= 1;

        // pack (edge0, edge1) lane-private values into f32x2 registers
        unsigned long long a[9], b[9];
#pragma unroll
        for (int i = 0; i < 9; ++i)
            a[i] = pk2(x1b[lane * 9 + i], x1b[ROW + lane * 9 + i]);
#pragma unroll
        for (int j = 0; j < 9; ++j)
            b[j] = pk2(bb[lane * 9 + j], bb[ROW + lane * 9 + j]);

        // group 1: k=0 (paths 0..2) — write into lane-private region of x1b
        {
            unsigned long long acc[1] = {0ULL};
            do_path2<0>(acc, a, b, wsm, lane);
            do_path2<1>(acc, a, b, wsm, lane);
            do_path2<2>(acc, a, b, wsm, lane);
            float lo, hi;
            upk2(lo, hi, acc[0]);
            x1b[lane * 9 + 0] = lo;
            x1b[ROW + lane * 9 + 0] = hi;
        }
        // group 2: k=1..3 (paths 3..6)
        {
            unsigned long long acc[3] = {0ULL, 0ULL, 0ULL};
            do_path2<3>(acc, a, b, wsm, lane);
            do_path2<4>(acc, a, b, wsm, lane);
            do_path2<5>(acc, a, b, wsm, lane);
            do_path2<6>(acc, a, b, wsm, lane);
#pragma unroll
            for (int kk = 0; kk < 3; ++kk) {
                float lo, hi;
                upk2(lo, hi, acc[kk]);
                x1b[lane * 9 + 1 + kk] = lo;
                x1b[ROW + lane * 9 + 1 + kk] = hi;
            }
        }
        // group 3: k=4..8 (paths 7..10)
        {
            unsigned long long acc[5] = {0ULL, 0ULL, 0ULL, 0ULL, 0ULL};
            do_path2<7>(acc, a, b, wsm, lane);
            do_path2<8>(acc, a, b, wsm, lane);
            do_path2<9>(acc, a, b, wsm, lane);
            do_path2<10>(acc, a, b, wsm, lane);
#pragma unroll
            for (int kk = 0; kk < 5; ++kk) {
                float lo, hi;
                upk2(lo, hi, acc[kk]);
                x1b[lane * 9 + 4 + kk] = lo;
                x1b[ROW + lane * 9 + 4 + kk] = hi;
            }
        }
        __syncwarp(); // all lanes' STS visible before the bulk store

        if (lane == 0) {
            asm volatile("fence.proxy.async.shared::cta;" ::: "memory");
            bulk_st(out + (size_t)e0 * ROW, x1s, 2 * ROWB);
            asm volatile("cp.async.bulk.commit_group;" ::: "memory");
        }
    }
    if (lane == 0)
        asm volatile("cp.async.bulk.wait_group 0;" ::: "memory");
}

// ---------------------------------------------------------------------------
// launch
// ---------------------------------------------------------------------------
extern "C" void kernel_launch(void* const* d_in, const int* in_sizes, int n_in,
                              void* d_out, int out_size) {
    const float* x1   = (const float*)d_in[0];
    const float* x2   = (const float*)d_in[1];
    const int*   idxs = (const int*)d_in[2];

    const float* w3j = nullptr;
    const float* weights = nullptr;
    for (int i = 3; i < n_in; ++i) {
        if (in_sizes[i] == NPATHS * 729) w3j = (const float*)d_in[i];
        else if (in_sizes[i] == MUL * NPATHS) weights = (const float*)d_in[i];
    }

    const int E = in_sizes[0] / ROW;
    float* out = (float*)d_out;

    // driver-optimized zeroing of the scatter buffer (graph memset node)
    void* scatter_dev = nullptr;
    cudaGetSymbolAddress(&scatter_dev, g_scatter);
    cudaMemsetAsync(scatter_dev, 0, (size_t)MAX_NODES * ROW * sizeof(float), 0);

    // scatter (MLP=2 per thread) + packed w3j extraction fused
    scatter_kernel<<<(E * HALF_CHUNKS + 255) / 256, 256>>>(x2, idxs, E, w3j);

    void* cval_dev = nullptr;
    cudaGetSymbolAddress(&cval_dev, g_cval2);
    cudaMemcpyToSymbolAsync(c_VAL2, cval_dev, 96 * sizeof(unsigned long long),
                            0, cudaMemcpyDeviceToDevice, 0);

    const int nPairs = E / 2; // E = 100000 (even)
    const int blocks = 592;   // 148 SMs * 4 blocks
    const int totalWarps = blocks * CWARPS;
    compute_kernel<<<blocks, CWARPS * 32>>>(x1, idxs, weights, out, nPairs,
                                            totalWarps);
}